// round 4
// baseline (speedup 1.0000x reference)
#include <cuda_runtime.h>

#define THREADS 256
#define CTA_M   64
#define KT      16
#define HID     512
#define LAT     64
#define LNEPS   1e-5f
#define TSTRIDE 257

__device__ __forceinline__ unsigned f2tf(float f) {
    unsigned u;
    asm("cvt.rna.tf32.f32 %0, %1;" : "=r"(u) : "f"(f));
    return u;
}

__device__ __forceinline__ void mma8(float c[4], unsigned a0, unsigned a1, unsigned a2, unsigned a3,
                                     unsigned b0, unsigned b1) {
    asm volatile(
        "mma.sync.aligned.m16n8k8.row.col.f32.tf32.tf32.f32 "
        "{%0,%1,%2,%3},{%4,%5,%6,%7},{%8,%9},{%0,%1,%2,%3};\n"
        : "+f"(c[0]), "+f"(c[1]), "+f"(c[2]), "+f"(c[3])
        : "r"(a0), "r"(a1), "r"(a2), "r"(a3), "r"(b0), "r"(b1));
}

// ---- weight chunk staging: gmem -> regs -> swizzled smem (tf32-rounded) ----
// smem layout per chunk: 8x8 tiles, tile(kstep,ntile) contiguous 64 floats,
// within-tile offset = kp*8 + (col ^ (kp&4))  -> conflict-free b-frag loads.
template<int N, bool HEADS>
__device__ __forceinline__ void ldg_chunk(float4* pf, const float* __restrict__ Bg, int k0, int tid) {
    constexpr int IT = KT * N / 4 / THREADS;
    int a = tid & 3;
    int k = (tid >> 2) & 15;
    int b = tid >> 6;
    #pragma unroll
    for (int i = 0; i < IT; i++) {
        int n = (a + (b << 2) + (i << 4)) << 2;
        const float* p;
        if (HEADS) p = Bg + (n >> 6) * (HID * 64) + (k0 + k) * 64 + (n & 63); // Wh1[h][k][d], n=h*64+d
        else       p = Bg + (k0 + k) * N + n;
        pf[i] = *reinterpret_cast<const float4*>(p);
    }
}

template<int N>
__device__ __forceinline__ void sts_chunk(const float4* pf, float* buf, int tid) {
    constexpr int IT = KT * N / 4 / THREADS;
    int a = tid & 3;
    int k = (tid >> 2) & 15;
    int b = tid >> 6;
    int kstep = k >> 3, kp = k & 7;
    #pragma unroll
    for (int i = 0; i < IT; i++) {
        int n = (a + (b << 2) + (i << 4)) << 2;
        int ntile = n >> 3;
        int swz = (n & 7) ^ (kp & 4);
        float4 v = pf[i];
        float4 w;
        w.x = __uint_as_float(f2tf(v.x));
        w.y = __uint_as_float(f2tf(v.y));
        w.z = __uint_as_float(f2tf(v.z));
        w.w = __uint_as_float(f2tf(v.w));
        *reinterpret_cast<float4*>(buf + (kstep * (N / 8) + ntile) * 64 + kp * 8 + swz) = w;
    }
}

// ---- mma over one staged chunk ----
template<int N>
__device__ __forceinline__ void mma_chunk(const float* Asm, int astride, const float* buf,
                                          float (*acc)[4], int wm, int wn, int lane, int k0) {
    constexpr int NT = N / 16;   // n-tiles per warp (warp covers N/2 columns)
    int g = lane >> 2, t = lane & 3;
    int row = wm * 16 + g;
    int s = g << 2;              // activation column swizzle: col ^ ((row&7)<<2), row&7==g
    #pragma unroll
    for (int ks = 0; ks < KT / 8; ks++) {
        int kA = k0 + ks * 8 + t;
        unsigned a0 = __float_as_uint(Asm[row * astride + (kA ^ s)]);
        unsigned a1 = __float_as_uint(Asm[(row + 8) * astride + (kA ^ s)]);
        unsigned a2 = __float_as_uint(Asm[row * astride + ((kA + 4) ^ s)]);
        unsigned a3 = __float_as_uint(Asm[(row + 8) * astride + ((kA + 4) ^ s)]);
        const float* tb = buf + ks * (N / 8) * 64 + wn * NT * 64;
        #pragma unroll
        for (int nt = 0; nt < NT; nt++) {
            const float* tp = tb + nt * 64;
            unsigned b0 = __float_as_uint(tp[t * 8 + g]);
            unsigned b1 = __float_as_uint(tp[(t + 4) * 8 + (g ^ 4)]);
            mma8(acc[nt], a0, a1, a2, a3, b0, b1);
        }
    }
}

template<int N, int KTOT, bool HEADS>
__device__ __forceinline__ void run_gemm(const float* Asm, int astride, const float* __restrict__ Bg,
                                         float* stage, float (*acc)[4], int tid) {
    constexpr int NC = KTOT / KT;
    constexpr int NT = N / 16;
    int warp = tid >> 5, lane = tid & 31;
    int wm = warp & 3, wn = warp >> 2;
    #pragma unroll
    for (int nt = 0; nt < NT; nt++) {
        #pragma unroll
        for (int j = 0; j < 4; j++) acc[nt][j] = 0.f;
    }
    float4 pf[8];
    ldg_chunk<N, HEADS>(pf, Bg, 0, tid);
    sts_chunk<N>(pf, stage, tid);
    __syncthreads();
    #pragma unroll 1
    for (int c = 0; c < NC; c++) {
        if (c + 1 < NC) ldg_chunk<N, HEADS>(pf, Bg, (c + 1) * KT, tid);
        mma_chunk<N>(Asm, astride, stage + (c & 1) * (KT * HID), acc, wm, wn, lane, c * KT);
        if (c + 1 < NC) sts_chunk<N>(pf, stage + ((c + 1) & 1) * (KT * HID), tid);
        __syncthreads();
    }
}

// store whole-N accumulators (N=512) into swizzled activation buffer
__device__ __forceinline__ void store_acc512(float (*acc)[4], float* sh, int tid) {
    int warp = tid >> 5, lane = tid & 31;
    int wm = warp & 3, wn = warp >> 2;
    int g = lane >> 2, t = lane & 3;
    int row = wm * 16 + g;
    int s = g << 2;
    #pragma unroll
    for (int nt = 0; nt < 32; nt++) {
        int col = wn * 256 + nt * 8 + 2 * t;
        int c0 = col ^ s;   // swizzle doesn't touch bit0/1 (col even), pair contiguous
        *reinterpret_cast<float2*>(sh + row * HID + c0)       = make_float2(acc[nt][0], acc[nt][1]);
        *reinterpret_cast<float2*>(sh + (row + 8) * HID + c0) = make_float2(acc[nt][2], acc[nt][3]);
    }
}

// in-place: h = leaky( LN(h + bias) * gamma + beta ), output rounded to tf32
__device__ __forceinline__ void layernorm_leaky(float* sh, const float* __restrict__ bias,
                                                const float* __restrict__ gam,
                                                const float* __restrict__ bet, int tid) {
    int warp = tid >> 5, lane = tid & 31;
    float pb[16], pg[16], pe[16];
    #pragma unroll
    for (int j = 0; j < 16; j++) {
        int k = lane + 32 * j;
        pb[j] = __ldg(bias + k);
        pg[j] = __ldg(gam + k);
        pe[j] = __ldg(bet + k);
    }
    #pragma unroll 1
    for (int r0 = 0; r0 < 8; r0++) {
        int r = warp * 8 + r0;
        int s = (r & 7) << 2;
        float v[16];
        float sum = 0.f, sq = 0.f;
        #pragma unroll
        for (int j = 0; j < 16; j++) {
            int k = lane + 32 * j;
            float x = sh[r * HID + (k ^ s)] + pb[j];
            v[j] = x;
            sum += x;
            sq = fmaf(x, x, sq);
        }
        #pragma unroll
        for (int o = 16; o > 0; o >>= 1) {
            sum += __shfl_xor_sync(0xffffffffu, sum, o);
            sq  += __shfl_xor_sync(0xffffffffu, sq,  o);
        }
        float mu = sum * (1.f / 512.f);
        float var = sq * (1.f / 512.f) - mu * mu;
        float rs = rsqrtf(var + LNEPS);
        #pragma unroll
        for (int j = 0; j < 16; j++) {
            int k = lane + 32 * j;
            float x = (v[j] - mu) * rs * pg[j] + pe[j];
            x = (x >= 0.f) ? x : 0.2f * x;
            sh[r * HID + (k ^ s)] = __uint_as_float(f2tf(x));
        }
    }
}

__global__ void __launch_bounds__(THREADS, 1)
eve_fused_kernel(const float* __restrict__ z, const int* __restrict__ xs, const int* __restrict__ ys,
                 const float* __restrict__ W1, const float* __restrict__ b1,
                 const float* __restrict__ g1, const float* __restrict__ be1,
                 const float* __restrict__ W2, const float* __restrict__ b2,
                 const float* __restrict__ g2, const float* __restrict__ be2,
                 const float* __restrict__ Wh1, const float* __restrict__ bh1,
                 const float* __restrict__ Wh2, const float* __restrict__ bh2,
                 float* __restrict__ out)
{
    extern __shared__ float smem[];
    float* sh    = smem;                      // 64*512 activation buffer (swizzled)
    float* stage = smem + CTA_M * HID;        // 2 * KT*HID weight chunks
    float* sz    = stage + 2 * KT * HID;      // 64*64 z tile (swizzled)
    float* tbuf  = stage;                     // reused for t[64][TSTRIDE] (overflows into sz)

    int tid = threadIdx.x;
    int cta_row = blockIdx.x * CTA_M;

    // load z tile, round to tf32, swizzle columns by row
    #pragma unroll
    for (int i = 0; i < 4; i++) {
        int idx = tid + i * THREADS;
        int r = idx >> 4;
        int k = (idx & 15) << 2;
        float4 v = *reinterpret_cast<const float4*>(z + (size_t)(cta_row + r) * LAT + k);
        float4 w;
        w.x = __uint_as_float(f2tf(v.x));
        w.y = __uint_as_float(f2tf(v.y));
        w.z = __uint_as_float(f2tf(v.z));
        w.w = __uint_as_float(f2tf(v.w));
        *reinterpret_cast<float4*>(sz + r * LAT + (k ^ ((r & 7) << 2))) = w;
    }
    __syncthreads();

    float acc[32][4];

    // ---- encoder layer 1: h = leaky(LN(z @ W1 + b1)) ----
    run_gemm<512, 64, false>(sz, LAT, W1, stage, acc, tid);
    store_acc512(acc, sh, tid);
    __syncthreads();
    layernorm_leaky(sh, b1, g1, be1, tid);
    __syncthreads();

    // ---- encoder layer 2: h = leaky(LN(h @ W2 + b2)) ----
    run_gemm<512, 512, false>(sh, HID, W2, stage, acc, tid);
    store_acc512(acc, sh, tid);
    __syncthreads();
    layernorm_leaky(sh, b2, g2, be2, tid);
    __syncthreads();

    // ---- all 4 heads layer 1: t = relu(h @ Wh1_cat + bh1), N = 256 ----
    run_gemm<256, 512, true>(sh, HID, Wh1, stage, acc, tid);
    {
        int warp = tid >> 5, lane = tid & 31;
        int wm = warp & 3, wn = warp >> 2;
        int g = lane >> 2, t = lane & 3;
        int row = wm * 16 + g;
        #pragma unroll
        for (int nt = 0; nt < 16; nt++) {
            int col = wn * 128 + nt * 8 + 2 * t;
            float bb0 = __ldg(bh1 + col);
            float bb1 = __ldg(bh1 + col + 1);
            // scalar stores: TSTRIDE is odd, float2 here would be misaligned
            tbuf[row * TSTRIDE + col]           = fmaxf(acc[nt][0] + bb0, 0.f);
            tbuf[row * TSTRIDE + col + 1]       = fmaxf(acc[nt][1] + bb1, 0.f);
            tbuf[(row + 8) * TSTRIDE + col]     = fmaxf(acc[nt][2] + bb0, 0.f);
            tbuf[(row + 8) * TSTRIDE + col + 1] = fmaxf(acc[nt][3] + bb1, 0.f);
        }
    }
    __syncthreads();

    // ---- selected head layer 2 (64->4) + softmax, one thread per row ----
    if (tid < CTA_M) {
        int gr = cta_row + tid;
        int hk = 2 * __ldg(xs + gr) + __ldg(ys + gr);
        const float* w  = Wh2 + hk * (64 * 4);
        const float* tr = tbuf + tid * TSTRIDE + hk * 64;
        float4 bb = *reinterpret_cast<const float4*>(bh2 + hk * 4);
        float l0 = bb.x, l1 = bb.y, l2 = bb.z, l3 = bb.w;
        #pragma unroll 8
        for (int d = 0; d < 64; d++) {
            float tv = tr[d];
            float4 wv = __ldg(reinterpret_cast<const float4*>(w + d * 4));
            l0 = fmaf(tv, wv.x, l0);
            l1 = fmaf(tv, wv.y, l1);
            l2 = fmaf(tv, wv.z, l2);
            l3 = fmaf(tv, wv.w, l3);
        }
        float m = fmaxf(fmaxf(l0, l1), fmaxf(l2, l3));
        float e0 = expf(l0 - m), e1 = expf(l1 - m), e2 = expf(l2 - m), e3 = expf(l3 - m);
        float inv = 1.f / (e0 + e1 + e2 + e3);
        *reinterpret_cast<float4*>(out + (size_t)gr * 4) =
            make_float4(e0 * inv, e1 * inv, e2 * inv, e3 * inv);
    }
}

extern "C" void kernel_launch(void* const* d_in, const int* in_sizes, int n_in,
                              void* d_out, int out_size) {
    (void)n_in; (void)out_size;
    const float* z   = (const float*)d_in[0];
    const int*   xs  = (const int*)d_in[1];
    const int*   ys  = (const int*)d_in[2];
    const float* W1  = (const float*)d_in[3];
    const float* b1  = (const float*)d_in[4];
    const float* g1  = (const float*)d_in[5];
    const float* be1 = (const float*)d_in[6];
    const float* W2  = (const float*)d_in[7];
    const float* b2  = (const float*)d_in[8];
    const float* g2  = (const float*)d_in[9];
    const float* be2 = (const float*)d_in[10];
    const float* Wh1 = (const float*)d_in[11];
    const float* bh1 = (const float*)d_in[12];
    const float* Wh2 = (const float*)d_in[13];
    const float* bh2 = (const float*)d_in[14];
    float* out = (float*)d_out;

    int Btot = in_sizes[1];              // x has B elements
    int grid = Btot / CTA_M;
    size_t smem = (size_t)(CTA_M * HID + 2 * KT * HID + CTA_M * LAT) * sizeof(float); // 212992 B
    cudaFuncSetAttribute(eve_fused_kernel, cudaFuncAttributeMaxDynamicSharedMemorySize, (int)smem);
    eve_fused_kernel<<<grid, THREADS, smem>>>(z, xs, ys, W1, b1, g1, be1,
                                              W2, b2, g2, be2, Wh1, bh1, Wh2, bh2, out);
}

// round 5
// speedup vs baseline: 1.1638x; 1.1638x over previous
#include <cuda_runtime.h>

#define THREADS 512
#define CTA_M   64
#define KT      16
#define HID     512
#define LAT     64
#define LNEPS   1e-5f
#define TSTRIDE 257
#define TILE_F  72   // 64-float 8x8 tile + 8 pad: conflict-free stores AND loads

__device__ __forceinline__ unsigned f2tf(float f) {
    unsigned u;
    asm("cvt.rna.tf32.f32 %0, %1;" : "=r"(u) : "f"(f));
    return u;
}

__device__ __forceinline__ void mma8(float c[4], unsigned a0, unsigned a1, unsigned a2, unsigned a3,
                                     unsigned b0, unsigned b1) {
    asm volatile(
        "mma.sync.aligned.m16n8k8.row.col.f32.tf32.tf32.f32 "
        "{%0,%1,%2,%3},{%4,%5,%6,%7},{%8,%9},{%0,%1,%2,%3};\n"
        : "+f"(c[0]), "+f"(c[1]), "+f"(c[2]), "+f"(c[3])
        : "r"(a0), "r"(a1), "r"(a2), "r"(a3), "r"(b0), "r"(b1));
}

// ---- weight staging: each thread loads rows (k, k+4) x one n-quad ----
// chunk smem layout: [kstep][ntile] tiles of TILE_F floats;
// within tile, element (kp, nc) at pos = (kp>>2)*32 + (kp&1)*16 + ((kp>>1)&1)*8 + nc.
// b-frag reads (b0: kp=t, b1: kp=t+4) and STS.128 stores are both bank-conflict-free.
template<int N, bool HEADS>
__device__ __forceinline__ void ldg_chunk(float4 (*pf)[2], const float* __restrict__ Bg, int k0, int tid) {
    constexpr int IT = N / 256;
    int w = tid >> 5, lane = tid & 31;
    int kstep = w & 1, kr = (w >> 1) & 3, half = w >> 3;
    int rA = k0 + kstep * 8 + kr;
    #pragma unroll
    for (int i = 0; i < IT; i++) {
        int nq = half * (IT * 32) + i * 32 + lane;
        int n = nq << 2;
        const float* pA;
        const float* pB;
        if (HEADS) {  // Wh1[4][HID][64], col n = head*64 + d
            pA = Bg + (n >> 6) * (HID * 64) + rA * 64 + (n & 63);
            pB = pA + 4 * 64;
        } else {
            pA = Bg + rA * N + n;
            pB = pA + 4 * N;
        }
        pf[i][0] = *reinterpret_cast<const float4*>(pA);
        pf[i][1] = *reinterpret_cast<const float4*>(pB);
    }
}

template<int N>
__device__ __forceinline__ void sts_chunk(const float4 (*pf)[2], float* buf, int tid) {
    constexpr int IT = N / 256;
    int w = tid >> 5, lane = tid & 31;
    int kstep = w & 1, kr = (w >> 1) & 3, half = w >> 3;
    #pragma unroll
    for (int i = 0; i < IT; i++) {
        int nq = half * (IT * 32) + i * 32 + lane;
        int nt = nq >> 1, ncb = nq & 1;
        float* tb = buf + (kstep * (N / 8) + nt) * TILE_F
                        + (kr & 1) * 16 + ((kr >> 1) & 1) * 8 + ncb * 4;
        float4 v = pf[i][0], u = pf[i][1];
        float4 vo, uo;
        vo.x = __uint_as_float(f2tf(v.x)); vo.y = __uint_as_float(f2tf(v.y));
        vo.z = __uint_as_float(f2tf(v.z)); vo.w = __uint_as_float(f2tf(v.w));
        uo.x = __uint_as_float(f2tf(u.x)); uo.y = __uint_as_float(f2tf(u.y));
        uo.z = __uint_as_float(f2tf(u.z)); uo.w = __uint_as_float(f2tf(u.w));
        *reinterpret_cast<float4*>(tb)      = vo;   // kh = 0 (rows k)
        *reinterpret_cast<float4*>(tb + 32) = uo;   // kh = 1 (rows k+4)
    }
}

// ---- mma over one staged chunk; warp = 2 m-tiles x (N/64) n-tiles ----
template<int N>
__device__ __forceinline__ void mma_chunk(const float* Asm, int astride, const float* buf,
                                          float (*acc)[4], int wm, int wn, int lane, int k0) {
    constexpr int NT = N / 64;
    int g = lane >> 2, t = lane & 3;
    int s = g << 2;
    int bpos = (t & 1) * 16 + (t >> 1) * 8 + g;
    #pragma unroll
    for (int ks = 0; ks < 2; ks++) {
        int kA = k0 + ks * 8 + t;
        unsigned a[2][4];
        #pragma unroll
        for (int mt = 0; mt < 2; mt++) {
            int row = wm * 32 + mt * 16 + g;
            a[mt][0] = __float_as_uint(Asm[row * astride + (kA ^ s)]);
            a[mt][1] = __float_as_uint(Asm[(row + 8) * astride + (kA ^ s)]);
            a[mt][2] = __float_as_uint(Asm[row * astride + ((kA + 4) ^ s)]);
            a[mt][3] = __float_as_uint(Asm[(row + 8) * astride + ((kA + 4) ^ s)]);
        }
        const float* tb = buf + (ks * (N / 8) + wn * NT) * TILE_F;
        #pragma unroll
        for (int nt = 0; nt < NT; nt++) {
            const float* tp = tb + nt * TILE_F;
            unsigned b0 = __float_as_uint(tp[bpos]);
            unsigned b1 = __float_as_uint(tp[bpos + 32]);
            mma8(acc[nt],      a[0][0], a[0][1], a[0][2], a[0][3], b0, b1);
            mma8(acc[NT + nt], a[1][0], a[1][1], a[1][2], a[1][3], b0, b1);
        }
    }
}

template<int N, int KTOT, bool HEADS>
__device__ __forceinline__ void run_gemm(const float* Asm, int astride, const float* __restrict__ Bg,
                                         float* stage, float (*acc)[4], int tid) {
    constexpr int NC = KTOT / KT;
    constexpr int NT2 = 2 * (N / 64);
    constexpr int CHUNKF = 2 * (N / 8) * TILE_F;
    int warp = tid >> 5, lane = tid & 31;
    int wm = warp & 1, wn = warp >> 1;
    #pragma unroll
    for (int i = 0; i < NT2; i++) {
        #pragma unroll
        for (int j = 0; j < 4; j++) acc[i][j] = 0.f;
    }
    float4 pf[2][2];
    ldg_chunk<N, HEADS>(pf, Bg, 0, tid);
    sts_chunk<N>(pf, stage, tid);
    __syncthreads();
    #pragma unroll 1
    for (int c = 0; c < NC; c++) {
        if (c + 1 < NC) ldg_chunk<N, HEADS>(pf, Bg, (c + 1) * KT, tid);
        mma_chunk<N>(Asm, astride, stage + (c & 1) * CHUNKF, acc, wm, wn, lane, c * KT);
        if (c + 1 < NC) sts_chunk<N>(pf, stage + ((c + 1) & 1) * CHUNKF, tid);
        __syncthreads();
    }
}

// store whole-N accumulators (N=512) into swizzled activation buffer
__device__ __forceinline__ void store_acc512(float (*acc)[4], float* sh, int tid) {
    int warp = tid >> 5, lane = tid & 31;
    int wm = warp & 1, wn = warp >> 1;
    int g = lane >> 2, t = lane & 3;
    int s = g << 2;
    #pragma unroll
    for (int mt = 0; mt < 2; mt++) {
        int row = wm * 32 + mt * 16 + g;
        #pragma unroll
        for (int nt = 0; nt < 8; nt++) {
            int col = wn * 64 + nt * 8 + 2 * t;
            int c0 = col ^ s;
            float* a = acc[mt * 8 + nt];
            *reinterpret_cast<float2*>(sh + row * HID + c0)       = make_float2(a[0], a[1]);
            *reinterpret_cast<float2*>(sh + (row + 8) * HID + c0) = make_float2(a[2], a[3]);
        }
    }
}

// in-place: h = leaky( LN(h + bias) * gamma + beta ), output rounded to tf32
__device__ __forceinline__ void layernorm_leaky(float* sh, const float* __restrict__ bias,
                                                const float* __restrict__ gam,
                                                const float* __restrict__ bet, int tid) {
    int warp = tid >> 5, lane = tid & 31;
    float pb[16], pg[16], pe[16];
    #pragma unroll
    for (int j = 0; j < 16; j++) {
        int k = lane + 32 * j;
        pb[j] = __ldg(bias + k);
        pg[j] = __ldg(gam + k);
        pe[j] = __ldg(bet + k);
    }
    #pragma unroll 1
    for (int r0 = 0; r0 < 4; r0++) {
        int r = warp * 4 + r0;
        int s = (r & 7) << 2;
        float v[16];
        float sum = 0.f, sq = 0.f;
        #pragma unroll
        for (int j = 0; j < 16; j++) {
            int k = lane + 32 * j;
            float x = sh[r * HID + (k ^ s)] + pb[j];
            v[j] = x;
            sum += x;
            sq = fmaf(x, x, sq);
        }
        #pragma unroll
        for (int o = 16; o > 0; o >>= 1) {
            sum += __shfl_xor_sync(0xffffffffu, sum, o);
            sq  += __shfl_xor_sync(0xffffffffu, sq,  o);
        }
        float mu = sum * (1.f / 512.f);
        float var = sq * (1.f / 512.f) - mu * mu;
        float rs = rsqrtf(var + LNEPS);
        #pragma unroll
        for (int j = 0; j < 16; j++) {
            int k = lane + 32 * j;
            float x = (v[j] - mu) * rs * pg[j] + pe[j];
            x = (x >= 0.f) ? x : 0.2f * x;
            sh[r * HID + (k ^ s)] = __uint_as_float(f2tf(x));
        }
    }
}

__global__ void __launch_bounds__(THREADS, 1)
eve_fused_kernel(const float* __restrict__ z, const int* __restrict__ xs, const int* __restrict__ ys,
                 const float* __restrict__ W1, const float* __restrict__ b1,
                 const float* __restrict__ g1, const float* __restrict__ be1,
                 const float* __restrict__ W2, const float* __restrict__ b2,
                 const float* __restrict__ g2, const float* __restrict__ be2,
                 const float* __restrict__ Wh1, const float* __restrict__ bh1,
                 const float* __restrict__ Wh2, const float* __restrict__ bh2,
                 float* __restrict__ out)
{
    extern __shared__ float smem[];
    float* sh    = smem;                            // 64*512 activations (col-swizzled)
    float* stage = smem + CTA_M * HID;              // 2 * 9216 weight chunk buffers
    float* sz    = stage + 2 * 2 * (HID / 8) * TILE_F;  // 64*64 z tile
    float* tbuf  = stage;                           // reused for t[64][TSTRIDE]

    int tid = threadIdx.x;
    int cta_row = blockIdx.x * CTA_M;

    // load z tile, round to tf32, swizzle columns by row
    #pragma unroll
    for (int i = 0; i < 2; i++) {
        int idx = tid + i * THREADS;
        int r = idx >> 4;
        int k = (idx & 15) << 2;
        float4 v = *reinterpret_cast<const float4*>(z + (size_t)(cta_row + r) * LAT + k);
        float4 w;
        w.x = __uint_as_float(f2tf(v.x));
        w.y = __uint_as_float(f2tf(v.y));
        w.z = __uint_as_float(f2tf(v.z));
        w.w = __uint_as_float(f2tf(v.w));
        *reinterpret_cast<float4*>(sz + r * LAT + (k ^ ((r & 7) << 2))) = w;
    }
    __syncthreads();

    float acc[16][4];

    // ---- encoder layer 1: h = leaky(LN(z @ W1 + b1)) ----
    run_gemm<512, 64, false>(sz, LAT, W1, stage, acc, tid);
    store_acc512(acc, sh, tid);
    __syncthreads();
    layernorm_leaky(sh, b1, g1, be1, tid);
    __syncthreads();

    // ---- encoder layer 2: h = leaky(LN(h @ W2 + b2)) ----
    run_gemm<512, 512, false>(sh, HID, W2, stage, acc, tid);
    store_acc512(acc, sh, tid);
    __syncthreads();
    layernorm_leaky(sh, b2, g2, be2, tid);
    __syncthreads();

    // ---- all 4 heads layer 1: t = relu(h @ Wh1_cat + bh1), N = 256 ----
    run_gemm<256, 512, true>(sh, HID, Wh1, stage, acc, tid);
    {
        int warp = tid >> 5, lane = tid & 31;
        int wm = warp & 1, wn = warp >> 1;
        int g = lane >> 2, t = lane & 3;
        #pragma unroll
        for (int mt = 0; mt < 2; mt++) {
            int row = wm * 32 + mt * 16 + g;
            #pragma unroll
            for (int nt = 0; nt < 4; nt++) {
                int col = wn * 32 + nt * 8 + 2 * t;
                float bb0 = __ldg(bh1 + col);
                float bb1 = __ldg(bh1 + col + 1);
                float* a = acc[mt * 4 + nt];
                tbuf[row * TSTRIDE + col]           = fmaxf(a[0] + bb0, 0.f);
                tbuf[row * TSTRIDE + col + 1]       = fmaxf(a[1] + bb1, 0.f);
                tbuf[(row + 8) * TSTRIDE + col]     = fmaxf(a[2] + bb0, 0.f);
                tbuf[(row + 8) * TSTRIDE + col + 1] = fmaxf(a[3] + bb1, 0.f);
            }
        }
    }
    __syncthreads();

    // ---- selected head layer 2 (64->4) + softmax, one thread per row ----
    if (tid < CTA_M) {
        int gr = cta_row + tid;
        int hk = 2 * __ldg(xs + gr) + __ldg(ys + gr);
        const float* w  = Wh2 + hk * (64 * 4);
        const float* tr = tbuf + tid * TSTRIDE + hk * 64;
        float4 bb = *reinterpret_cast<const float4*>(bh2 + hk * 4);
        float l0 = bb.x, l1 = bb.y, l2 = bb.z, l3 = bb.w;
        #pragma unroll 8
        for (int d = 0; d < 64; d++) {
            float tv = tr[d];
            float4 wv = __ldg(reinterpret_cast<const float4*>(w + d * 4));
            l0 = fmaf(tv, wv.x, l0);
            l1 = fmaf(tv, wv.y, l1);
            l2 = fmaf(tv, wv.z, l2);
            l3 = fmaf(tv, wv.w, l3);
        }
        float m = fmaxf(fmaxf(l0, l1), fmaxf(l2, l3));
        float e0 = expf(l0 - m), e1 = expf(l1 - m), e2 = expf(l2 - m), e3 = expf(l3 - m);
        float inv = 1.f / (e0 + e1 + e2 + e3);
        *reinterpret_cast<float4*>(out + (size_t)gr * 4) =
            make_float4(e0 * inv, e1 * inv, e2 * inv, e3 * inv);
    }
}

extern "C" void kernel_launch(void* const* d_in, const int* in_sizes, int n_in,
                              void* d_out, int out_size) {
    (void)n_in; (void)out_size;
    const float* z   = (const float*)d_in[0];
    const int*   xs  = (const int*)d_in[1];
    const int*   ys  = (const int*)d_in[2];
    const float* W1  = (const float*)d_in[3];
    const float* b1  = (const float*)d_in[4];
    const float* g1  = (const float*)d_in[5];
    const float* be1 = (const float*)d_in[6];
    const float* W2  = (const float*)d_in[7];
    const float* b2  = (const float*)d_in[8];
    const float* g2  = (const float*)d_in[9];
    const float* be2 = (const float*)d_in[10];
    const float* Wh1 = (const float*)d_in[11];
    const float* bh1 = (const float*)d_in[12];
    const float* Wh2 = (const float*)d_in[13];
    const float* bh2 = (const float*)d_in[14];
    float* out = (float*)d_out;

    int Btot = in_sizes[1];              // x has B elements
    int grid = Btot / CTA_M;
    // 64*512 + 2*9216 + 64*64 = 55296 floats = 221184 bytes
    size_t smem = (size_t)(CTA_M * HID + 2 * 2 * (HID / 8) * TILE_F + CTA_M * LAT) * sizeof(float);
    cudaFuncSetAttribute(eve_fused_kernel, cudaFuncAttributeMaxDynamicSharedMemorySize, (int)smem);
    eve_fused_kernel<<<grid, THREADS, smem>>>(z, xs, ys, W1, b1, g1, be1,
                                              W2, b2, g2, be2, Wh1, bh1, Wh2, bh2, out);
}